// round 5
// baseline (speedup 1.0000x reference)
#include <cuda_runtime.h>
#include <cuda_bf16.h>

// Levinson-Durbin, M=24. FOUR rows per thread: 2 sequential packed-f32x2
// recursions (each instruction serves 2 independent rows).
// out[row] = [K, a0..a23],  R a = -r1,  K = sqrt(E_24).
//
// R4 design (fixes R2's packing attempt with R3's wave structure):
//  - TPB=64, 256 rows/CTA, grid=1024 -> 6.9 CTAs/SM needed, ~8 fit at
//    ~118 regs -> SINGLE WAVE, all threads resident, ~1% imbalance.
//  - f32x2 fma/mul/add halve per-row issued instruction count (the kernel
//    is issue-count bound: R3 = 10.6M warp-instrs @ 61.7% issue).
//  - cp.async prefetch of all 4 tiles; staged wait_group overlaps pair-2's
//    copy with pair-1's compute. Outputs staged into consumed input tiles.
//  - recursion: 2-way split packed dot, pipelined rcp(-E), E += k*acc.

constexpr int M_ORD = 24;
constexpr int NC    = M_ORD + 1;              // 25
constexpr int TPB   = 64;
constexpr int ROWS_PER_TILE = TPB;            // 64
constexpr int RPB   = 4 * ROWS_PER_TILE;      // 256 rows per CTA
constexpr int TILE_FLOATS = ROWS_PER_TILE * NC;   // 1600
constexpr int TILE_V4     = TILE_FLOATS / 4;      // 400

using u64 = unsigned long long;

__device__ __forceinline__ void cp_async16(unsigned saddr, const void* gaddr) {
    asm volatile("cp.async.cg.shared.global [%0], [%1], 16;"
                 :: "r"(saddr), "l"(gaddr));
}
__device__ __forceinline__ void cp_commit() {
    asm volatile("cp.async.commit_group;");
}
template <int N>
__device__ __forceinline__ void cp_wait() {
    asm volatile("cp.async.wait_group %0;" :: "n"(N));
}

__device__ __forceinline__ u64 pack2(float lo, float hi) {
    u64 d; asm("mov.b64 %0, {%1, %2};" : "=l"(d) : "f"(lo), "f"(hi)); return d;
}
__device__ __forceinline__ void unpack2(u64 x, float& lo, float& hi) {
    asm("mov.b64 {%0, %1}, %2;" : "=f"(lo), "=f"(hi) : "l"(x));
}
__device__ __forceinline__ u64 fma2(u64 a, u64 b, u64 c) {
    u64 d; asm("fma.rn.f32x2 %0, %1, %2, %3;" : "=l"(d) : "l"(a), "l"(b), "l"(c)); return d;
}
__device__ __forceinline__ u64 mul2(u64 a, u64 b) {
    u64 d; asm("mul.rn.f32x2 %0, %1, %2;" : "=l"(d) : "l"(a), "l"(b)); return d;
}
__device__ __forceinline__ u64 add2(u64 a, u64 b) {
    u64 d; asm("add.rn.f32x2 %0, %1, %2;" : "=l"(d) : "l"(a), "l"(b)); return d;
}
// -(1/x): negation folded into the MUFU operand
__device__ __forceinline__ float nrcp(float x) {
    float y; asm("rcp.approx.f32 %0, %1;" : "=f"(y) : "f"(-x)); return y;
}

// Packed recursion over two independent rows. rr in, a out, returns packed E.
__device__ __forceinline__ u64 levdur2(const u64 rr[NC], u64 a[M_ORD]) {
    u64 E = rr[0];
    u64 ninvE;                           // packed { -1/E_lo, -1/E_hi }
    {
        float el, eh; unpack2(E, el, eh);
        ninvE = pack2(nrcp(el), nrcp(eh));
    }
    #pragma unroll
    for (int m = 0; m < M_ORD; m++) {
        // acc = rr[m+1] + sum_i a[i]*rr[m-i]   (2-way split packed)
        u64 s0 = rr[m + 1];
        u64 s1 = 0ULL;
        #pragma unroll
        for (int i = 0; i + 1 < m; i += 2) {
            s0 = fma2(a[i    ], rr[m - i    ], s0);
            s1 = fma2(a[i + 1], rr[m - i - 1], s1);
        }
        if (m & 1) s0 = fma2(a[m - 1], rr[1], s0);
        u64 acc = add2(s0, s1);

        u64 k = mul2(acc, ninvE);        // k = -acc/E (MUFU hidden)

        // symmetric in-place update: a_i' = a_i + k * a_{m-1-i}
        #pragma unroll
        for (int i = 0; i < m / 2; i++) {
            u64 t = a[i];
            u64 u = a[m - 1 - i];
            a[i]         = fma2(k, u, t);
            a[m - 1 - i] = fma2(k, t, u);
        }
        if (m & 1) {
            u64 t = a[m / 2];
            a[m / 2] = fma2(k, t, t);
        }
        a[m] = k;

        E = fma2(k, acc, E);             // E *= (1 - k^2)
        float el, eh; unpack2(E, el, eh);
        ninvE = pack2(nrcp(el), nrcp(eh));   // hides under next dot
    }
    return E;
}

__global__ __launch_bounds__(TPB, 7)
void levinson_durbin_kernel(const float* __restrict__ r,
                            float* __restrict__ out,
                            int nrows)
{
    __shared__ float sbuf[4][TILE_FLOATS];   // 25.6 KB
    const int tid  = threadIdx.x;
    const int row0 = blockIdx.x * RPB;

    if (row0 + RPB <= nrows) {
        // ---- async prefetch of all 4 tiles (one commit group each) ----
        #pragma unroll
        for (int t = 0; t < 4; t++) {
            unsigned s = (unsigned)__cvta_generic_to_shared(&sbuf[t][0]);
            const float4* g = reinterpret_cast<const float4*>(
                r + (size_t)(row0 + t * ROWS_PER_TILE) * NC);
            #pragma unroll
            for (int i = tid; i < TILE_V4; i += TPB)
                cp_async16(s + i * 16, g + i);
            cp_commit();
        }

        #pragma unroll
        for (int p = 0; p < 2; p++) {    // pair p uses tiles 2p, 2p+1
            if (p == 0) cp_wait<2>(); else cp_wait<0>();
            __syncthreads();

            u64 rr[NC];
            #pragma unroll
            for (int i = 0; i < NC; i++)
                rr[i] = pack2(sbuf[2 * p    ][tid * NC + i],
                              sbuf[2 * p + 1][tid * NC + i]);

            u64 a[M_ORD];
            u64 E = levdur2(rr, a);
            float el, eh; unpack2(E, el, eh);

            // stage outputs into the consumed tiles (own rows only)
            sbuf[2 * p    ][tid * NC + 0] = sqrtf(el);
            sbuf[2 * p + 1][tid * NC + 0] = sqrtf(eh);
            #pragma unroll
            for (int i = 0; i < M_ORD; i++) {
                float lo, hi; unpack2(a[i], lo, hi);
                sbuf[2 * p    ][tid * NC + 1 + i] = lo;
                sbuf[2 * p + 1][tid * NC + 1 + i] = hi;
            }
            __syncthreads();

            // coalesced stores of both tiles
            #pragma unroll
            for (int t = 2 * p; t < 2 * p + 2; t++) {
                float4* o = reinterpret_cast<float4*>(
                    out + (size_t)(row0 + t * ROWS_PER_TILE) * NC);
                const float4* sb = reinterpret_cast<const float4*>(&sbuf[t][0]);
                #pragma unroll
                for (int i = tid; i < TILE_V4; i += TPB) o[i] = sb[i];
            }
        }
    } else {
        // generic scalar tail path (not hit for BATCH=262144)
        #pragma unroll
        for (int t = 0; t < 4; t++) {
            int row = row0 + t * ROWS_PER_TILE + tid;
            if (row >= nrows) continue;
            float rr[NC];
            #pragma unroll
            for (int i = 0; i < NC; i++) rr[i] = r[(size_t)row * NC + i];
            float a[M_ORD];
            float E = rr[0];
            float ninvE = nrcp(E);
            #pragma unroll
            for (int m = 0; m < M_ORD; m++) {
                float s0 = rr[m + 1], s1 = 0.0f;
                #pragma unroll
                for (int i = 0; i + 1 < m; i += 2) {
                    s0 = fmaf(a[i    ], rr[m - i    ], s0);
                    s1 = fmaf(a[i + 1], rr[m - i - 1], s1);
                }
                if (m & 1) s0 = fmaf(a[m - 1], rr[1], s0);
                float acc = s0 + s1;
                float k = acc * ninvE;
                #pragma unroll
                for (int i = 0; i < m / 2; i++) {
                    float x = a[i], y = a[m - 1 - i];
                    a[i]         = fmaf(k, y, x);
                    a[m - 1 - i] = fmaf(k, x, y);
                }
                if (m & 1) { float x = a[m / 2]; a[m / 2] = fmaf(k, x, x); }
                a[m] = k;
                E = fmaf(k, acc, E);
                ninvE = nrcp(E);
            }
            out[(size_t)row * NC + 0] = sqrtf(E);
            #pragma unroll
            for (int i = 0; i < M_ORD; i++)
                out[(size_t)row * NC + 1 + i] = a[i];
        }
    }
}

extern "C" void kernel_launch(void* const* d_in, const int* in_sizes, int n_in,
                              void* d_out, int out_size)
{
    const float* r = (const float*)d_in[0];
    float* out = (float*)d_out;
    const int nrows = in_sizes[0] / NC;
    const int grid = (nrows + RPB - 1) / RPB;
    levinson_durbin_kernel<<<grid, TPB>>>(r, out, nrows);
}

// round 6
// speedup vs baseline: 1.1165x; 1.1165x over previous
#include <cuda_runtime.h>
#include <cuda_bf16.h>

// Levinson-Durbin, M=24. ONE row per thread, TPB=64.
// out[row] = [K, a0..a23],  R a = -r1,  K = sqrt(E_24).
//
// R5 design (from R3 post-mortem: grid-limited occupancy, fma-pipe ~63%):
//  - 1 row/thread, grid=4096 small CTAs -> reg-cap occupancy (16 CTAs/SM,
//    8 warps/SMSP) instead of grid-limited 6.9 CTAs/SM. ~1.73 waves of
//    fine-grained CTAs rebalance via work-stealing.
//  - sqrt.approx for K (saves the IEEE-sqrt refinement sequence).
//  - cp.async staging, 4-split dot, pipelined rcp(-E), E += k*acc (as R3).

constexpr int M_ORD = 24;
constexpr int NC    = M_ORD + 1;            // 25
constexpr int TPB   = 64;
constexpr int RPB   = TPB;                  // 64 rows per CTA
constexpr int TILE_FLOATS = RPB * NC;       // 1600
constexpr int TILE_V4     = TILE_FLOATS / 4; // 400

__device__ __forceinline__ void cp_async16(unsigned saddr, const void* gaddr) {
    asm volatile("cp.async.cg.shared.global [%0], [%1], 16;"
                 :: "r"(saddr), "l"(gaddr));
}
__device__ __forceinline__ void cp_commit() {
    asm volatile("cp.async.commit_group;");
}
template <int N>
__device__ __forceinline__ void cp_wait() {
    asm volatile("cp.async.wait_group %0;" :: "n"(N));
}
// -(1/x): negation folded into the MUFU operand
__device__ __forceinline__ float nrcp(float x) {
    float y; asm("rcp.approx.f32 %0, %1;" : "=f"(y) : "f"(-x)); return y;
}
__device__ __forceinline__ float fsqrt_fast(float x) {
    float y; asm("sqrt.approx.f32 %0, %1;" : "=f"(y) : "f"(x)); return y;
}

// Full Levinson-Durbin recursion; returns K = sqrt(E_M), fills a[0..23].
__device__ __forceinline__ float levdur(const float rr[NC], float a[M_ORD]) {
    float E     = rr[0];
    float ninvE = nrcp(E);                  // -1/E, pipelined one iter ahead
    #pragma unroll
    for (int m = 0; m < M_ORD; m++) {
        // acc = rr[m+1] + sum_i a[i]*rr[m-i], 4-way split accumulators
        float s0 = rr[m + 1], s1 = 0.0f, s2 = 0.0f, s3 = 0.0f;
        #pragma unroll
        for (int i = 0; i + 3 < m; i += 4) {
            s0 = fmaf(a[i    ], rr[m - i    ], s0);
            s1 = fmaf(a[i + 1], rr[m - i - 1], s1);
            s2 = fmaf(a[i + 2], rr[m - i - 2], s2);
            s3 = fmaf(a[i + 3], rr[m - i - 3], s3);
        }
        {
            int i = m & ~3;
            if (i     < m) s0 = fmaf(a[i    ], rr[m - i    ], s0);
            if (i + 1 < m) s1 = fmaf(a[i + 1], rr[m - i - 1], s1);
            if (i + 2 < m) s2 = fmaf(a[i + 2], rr[m - i - 2], s2);
        }
        float acc = (s0 + s1) + (s2 + s3);

        float k = acc * ninvE;              // k = -acc/E (MUFU latency hidden)

        // symmetric in-place update: a_i' = a_i + k * a_{m-1-i}
        #pragma unroll
        for (int i = 0; i < m / 2; i++) {
            float t = a[i];
            float u = a[m - 1 - i];
            a[i]         = fmaf(k, u, t);
            a[m - 1 - i] = fmaf(k, t, u);
        }
        if (m & 1) {
            float t = a[m / 2];
            a[m / 2] = fmaf(k, t, t);
        }
        a[m] = k;

        E     = fmaf(k, acc, E);            // E *= (1 - k^2)
        ninvE = nrcp(E);                    // hides under next dot
    }
    return fsqrt_fast(E);
}

__global__ __launch_bounds__(TPB, 16)
void levinson_durbin_kernel(const float* __restrict__ r,
                            float* __restrict__ out,
                            int nrows)
{
    __shared__ float sbuf[TILE_FLOATS];     // 6.4 KB
    const int tid  = threadIdx.x;
    const int row0 = blockIdx.x * RPB;

    float rr[NC];
    float a[M_ORD];

    if (row0 + RPB <= nrows) {
        // ---- async prefetch of the 64-row tile (coalesced 16B chunks) ----
        unsigned s = (unsigned)__cvta_generic_to_shared(&sbuf[0]);
        const float4* g = reinterpret_cast<const float4*>(r + (size_t)row0 * NC);
        #pragma unroll
        for (int i = tid; i < TILE_V4; i += TPB) cp_async16(s + i * 16, g + i);
        cp_commit();
        cp_wait<0>();
        __syncthreads();

        // stride-25 (odd) per-thread reads: bank-conflict-free
        #pragma unroll
        for (int i = 0; i < NC; i++) rr[i] = sbuf[tid * NC + i];

        float Kv = levdur(rr, a);

        // stage output into own row (no sync needed before: owner-only)
        sbuf[tid * NC + 0] = Kv;
        #pragma unroll
        for (int i = 0; i < M_ORD; i++) sbuf[tid * NC + 1 + i] = a[i];
        __syncthreads();

        // coalesced vector store
        float4* o = reinterpret_cast<float4*>(out + (size_t)row0 * NC);
        const float4* sb = reinterpret_cast<const float4*>(&sbuf[0]);
        #pragma unroll
        for (int i = tid; i < TILE_V4; i += TPB) o[i] = sb[i];
    } else {
        // generic tail path (not hit for BATCH=262144)
        int row = row0 + tid;
        if (row < nrows) {
            #pragma unroll
            for (int i = 0; i < NC; i++) rr[i] = r[(size_t)row * NC + i];
            float Kv = levdur(rr, a);
            out[(size_t)row * NC + 0] = Kv;
            #pragma unroll
            for (int i = 0; i < M_ORD; i++)
                out[(size_t)row * NC + 1 + i] = a[i];
        }
    }
}

extern "C" void kernel_launch(void* const* d_in, const int* in_sizes, int n_in,
                              void* d_out, int out_size)
{
    const float* r = (const float*)d_in[0];
    float* out = (float*)d_out;
    const int nrows = in_sizes[0] / NC;
    const int grid = (nrows + RPB - 1) / RPB;
    levinson_durbin_kernel<<<grid, TPB>>>(r, out, nrows);
}

// round 7
// speedup vs baseline: 1.1189x; 1.0021x over previous
#include <cuda_runtime.h>
#include <cuda_bf16.h>

// Levinson-Durbin, M=24. ONE row per thread, ONE WARP per CTA.
// out[row] = [K, a0..a23],  R a = -r1,  K = sqrt(E_24).
//
// R6 design (from R5 accounting: fma pipe ~70% busy is the ceiling):
//  - TPB=32 (warp-sized CTAs), grid=8192: 32 CTAs/SM resident (CTA-slot
//    limit) = 32 warps = max occupancy for this reg count; 3.46 CTAs per
//    slot-wave lets CLC work-stealing erase the wave tail that held R5's
//    achieved occupancy to 39%.
//  - __syncwarp instead of block barriers (1-warp CTA).
//  - adaptive split accumulators: 2-way for m<=8 (saves reduction FADDs,
//    which share the fma pipe), 4-way for m>8 (keeps the chain short).
//  - cp.async staging, pipelined rcp(-E), E += k*acc, sqrt.approx (as R5).

constexpr int M_ORD = 24;
constexpr int NC    = M_ORD + 1;             // 25
constexpr int TPB   = 32;
constexpr int RPB   = TPB;                   // 32 rows per CTA
constexpr int TILE_FLOATS = RPB * NC;        // 800
constexpr int TILE_V4     = TILE_FLOATS / 4; // 200

__device__ __forceinline__ void cp_async16(unsigned saddr, const void* gaddr) {
    asm volatile("cp.async.cg.shared.global [%0], [%1], 16;"
                 :: "r"(saddr), "l"(gaddr));
}
__device__ __forceinline__ void cp_commit() {
    asm volatile("cp.async.commit_group;");
}
template <int N>
__device__ __forceinline__ void cp_wait() {
    asm volatile("cp.async.wait_group %0;" :: "n"(N));
}
// -(1/x): negation folded into the MUFU operand
__device__ __forceinline__ float nrcp(float x) {
    float y; asm("rcp.approx.f32 %0, %1;" : "=f"(y) : "f"(-x)); return y;
}
__device__ __forceinline__ float fsqrt_fast(float x) {
    float y; asm("sqrt.approx.f32 %0, %1;" : "=f"(y) : "f"(x)); return y;
}

// Full Levinson-Durbin recursion; returns K = sqrt(E_M), fills a[0..23].
__device__ __forceinline__ float levdur(const float rr[NC], float a[M_ORD]) {
    float E     = rr[0];
    float ninvE = nrcp(E);                   // -1/E, pipelined one iter ahead
    #pragma unroll
    for (int m = 0; m < M_ORD; m++) {
        float acc;
        if (m <= 8) {
            // short dots: 2-way split (1 reduction add)
            float s0 = rr[m + 1], s1 = 0.0f;
            #pragma unroll
            for (int i = 0; i + 1 < m; i += 2) {
                s0 = fmaf(a[i    ], rr[m - i    ], s0);
                s1 = fmaf(a[i + 1], rr[m - i - 1], s1);
            }
            if (m & 1) s0 = fmaf(a[m - 1], rr[1], s0);
            acc = s0 + s1;
        } else {
            // long dots: 4-way split (3 reduction adds, short chain)
            float s0 = rr[m + 1], s1 = 0.0f, s2 = 0.0f, s3 = 0.0f;
            #pragma unroll
            for (int i = 0; i + 3 < m; i += 4) {
                s0 = fmaf(a[i    ], rr[m - i    ], s0);
                s1 = fmaf(a[i + 1], rr[m - i - 1], s1);
                s2 = fmaf(a[i + 2], rr[m - i - 2], s2);
                s3 = fmaf(a[i + 3], rr[m - i - 3], s3);
            }
            {
                int i = m & ~3;
                if (i     < m) s0 = fmaf(a[i    ], rr[m - i    ], s0);
                if (i + 1 < m) s1 = fmaf(a[i + 1], rr[m - i - 1], s1);
                if (i + 2 < m) s2 = fmaf(a[i + 2], rr[m - i - 2], s2);
            }
            acc = (s0 + s1) + (s2 + s3);
        }

        float k = acc * ninvE;               // k = -acc/E (MUFU latency hidden)

        // symmetric in-place update: a_i' = a_i + k * a_{m-1-i}
        #pragma unroll
        for (int i = 0; i < m / 2; i++) {
            float t = a[i];
            float u = a[m - 1 - i];
            a[i]         = fmaf(k, u, t);
            a[m - 1 - i] = fmaf(k, t, u);
        }
        if (m & 1) {
            float t = a[m / 2];
            a[m / 2] = fmaf(k, t, t);
        }
        a[m] = k;

        E     = fmaf(k, acc, E);             // E *= (1 - k^2)
        ninvE = nrcp(E);                     // hides under next dot
    }
    return fsqrt_fast(E);
}

__global__ __launch_bounds__(TPB)
void levinson_durbin_kernel(const float* __restrict__ r,
                            float* __restrict__ out,
                            int nrows)
{
    __shared__ float sbuf[TILE_FLOATS];      // 3.2 KB
    const int tid  = threadIdx.x;
    const int row0 = blockIdx.x * RPB;

    float rr[NC];
    float a[M_ORD];

    if (row0 + RPB <= nrows) {
        // ---- async prefetch of the 32-row tile (coalesced 16B chunks) ----
        unsigned s = (unsigned)__cvta_generic_to_shared(&sbuf[0]);
        const float4* g = reinterpret_cast<const float4*>(r + (size_t)row0 * NC);
        #pragma unroll
        for (int i = tid; i < TILE_V4; i += TPB) cp_async16(s + i * 16, g + i);
        cp_commit();
        cp_wait<0>();
        __syncwarp();

        // stride-25 (odd) per-thread reads: bank-conflict-free
        #pragma unroll
        for (int i = 0; i < NC; i++) rr[i] = sbuf[tid * NC + i];

        float Kv = levdur(rr, a);

        // stage output into own row (owner-only writes)
        sbuf[tid * NC + 0] = Kv;
        #pragma unroll
        for (int i = 0; i < M_ORD; i++) sbuf[tid * NC + 1 + i] = a[i];
        __syncwarp();

        // coalesced vector store
        float4* o = reinterpret_cast<float4*>(out + (size_t)row0 * NC);
        const float4* sb = reinterpret_cast<const float4*>(&sbuf[0]);
        #pragma unroll
        for (int i = tid; i < TILE_V4; i += TPB) o[i] = sb[i];
    } else {
        // generic tail path (not hit for BATCH=262144)
        int row = row0 + tid;
        if (row < nrows) {
            #pragma unroll
            for (int i = 0; i < NC; i++) rr[i] = r[(size_t)row * NC + i];
            float Kv = levdur(rr, a);
            out[(size_t)row * NC + 0] = Kv;
            #pragma unroll
            for (int i = 0; i < M_ORD; i++)
                out[(size_t)row * NC + 1 + i] = a[i];
        }
    }
}

extern "C" void kernel_launch(void* const* d_in, const int* in_sizes, int n_in,
                              void* d_out, int out_size)
{
    const float* r = (const float*)d_in[0];
    float* out = (float*)d_out;
    const int nrows = in_sizes[0] / NC;
    const int grid = (nrows + RPB - 1) / RPB;
    levinson_durbin_kernel<<<grid, TPB>>>(r, out, nrows);
}

// round 8
// speedup vs baseline: 1.1382x; 1.0173x over previous
#include <cuda_runtime.h>
#include <cuda_bf16.h>

// Levinson-Durbin, M=24. ONE row per thread, ONE WARP per CTA, TWO tiles
// per CTA with a cp.async double-buffer pipeline.
// out[row] = [K, a0..a23],  R a = -r1,  K = sqrt(E_24).
//
// R7 design (R6 granularity + R3 pipelining):
//  - TPB=32, 64 rows/CTA, grid=4096 -> 27.7 warp-CTAs/SM resident in ONE
//    wave (no churn, no tail; RF caps residency at ~34 warps anyway).
//  - both tiles prefetched at CTA start: tile-B DRAM latency hides under
//    tile-A compute; tile-A store overlaps tile-B compute.
//  - adaptive split dot, pipelined rcp(-E), E += k*acc, sqrt.approx.

constexpr int M_ORD = 24;
constexpr int NC    = M_ORD + 1;             // 25
constexpr int TPB   = 32;
constexpr int ROWS_PER_TILE = TPB;           // 32
constexpr int RPB   = 2 * ROWS_PER_TILE;     // 64 rows per CTA
constexpr int TILE_FLOATS = ROWS_PER_TILE * NC;   // 800
constexpr int TILE_V4     = TILE_FLOATS / 4;      // 200

__device__ __forceinline__ void cp_async16(unsigned saddr, const void* gaddr) {
    asm volatile("cp.async.cg.shared.global [%0], [%1], 16;"
                 :: "r"(saddr), "l"(gaddr));
}
__device__ __forceinline__ void cp_commit() {
    asm volatile("cp.async.commit_group;");
}
template <int N>
__device__ __forceinline__ void cp_wait() {
    asm volatile("cp.async.wait_group %0;" :: "n"(N));
}
// -(1/x): negation folded into the MUFU operand
__device__ __forceinline__ float nrcp(float x) {
    float y; asm("rcp.approx.f32 %0, %1;" : "=f"(y) : "f"(-x)); return y;
}
__device__ __forceinline__ float fsqrt_fast(float x) {
    float y; asm("sqrt.approx.f32 %0, %1;" : "=f"(y) : "f"(x)); return y;
}

// Full Levinson-Durbin recursion; returns K = sqrt(E_M), fills a[0..23].
__device__ __forceinline__ float levdur(const float rr[NC], float a[M_ORD]) {
    float E     = rr[0];
    float ninvE = nrcp(E);                   // -1/E, pipelined one iter ahead
    #pragma unroll
    for (int m = 0; m < M_ORD; m++) {
        float acc;
        if (m <= 8) {
            float s0 = rr[m + 1], s1 = 0.0f;
            #pragma unroll
            for (int i = 0; i + 1 < m; i += 2) {
                s0 = fmaf(a[i    ], rr[m - i    ], s0);
                s1 = fmaf(a[i + 1], rr[m - i - 1], s1);
            }
            if (m & 1) s0 = fmaf(a[m - 1], rr[1], s0);
            acc = s0 + s1;
        } else {
            float s0 = rr[m + 1], s1 = 0.0f, s2 = 0.0f, s3 = 0.0f;
            #pragma unroll
            for (int i = 0; i + 3 < m; i += 4) {
                s0 = fmaf(a[i    ], rr[m - i    ], s0);
                s1 = fmaf(a[i + 1], rr[m - i - 1], s1);
                s2 = fmaf(a[i + 2], rr[m - i - 2], s2);
                s3 = fmaf(a[i + 3], rr[m - i - 3], s3);
            }
            {
                int i = m & ~3;
                if (i     < m) s0 = fmaf(a[i    ], rr[m - i    ], s0);
                if (i + 1 < m) s1 = fmaf(a[i + 1], rr[m - i - 1], s1);
                if (i + 2 < m) s2 = fmaf(a[i + 2], rr[m - i - 2], s2);
            }
            acc = (s0 + s1) + (s2 + s3);
        }

        float k = acc * ninvE;               // k = -acc/E (MUFU latency hidden)

        // symmetric in-place update: a_i' = a_i + k * a_{m-1-i}
        #pragma unroll
        for (int i = 0; i < m / 2; i++) {
            float t = a[i];
            float u = a[m - 1 - i];
            a[i]         = fmaf(k, u, t);
            a[m - 1 - i] = fmaf(k, t, u);
        }
        if (m & 1) {
            float t = a[m / 2];
            a[m / 2] = fmaf(k, t, t);
        }
        a[m] = k;

        E     = fmaf(k, acc, E);             // E *= (1 - k^2)
        ninvE = nrcp(E);                     // hides under next dot
    }
    return fsqrt_fast(E);
}

__global__ __launch_bounds__(TPB)
void levinson_durbin_kernel(const float* __restrict__ r,
                            float* __restrict__ out,
                            int nrows)
{
    __shared__ float sbuf[2][TILE_FLOATS];   // 6.4 KB
    const int tid  = threadIdx.x;
    const int row0 = blockIdx.x * RPB;

    float rr[NC];
    float a[M_ORD];

    if (row0 + RPB <= nrows) {
        // ---- prefetch BOTH 32-row tiles (separate commit groups) ----
        unsigned s0 = (unsigned)__cvta_generic_to_shared(&sbuf[0][0]);
        unsigned s1 = (unsigned)__cvta_generic_to_shared(&sbuf[1][0]);
        const float4* g0 = reinterpret_cast<const float4*>(r + (size_t)row0 * NC);
        const float4* g1 = reinterpret_cast<const float4*>(
            r + (size_t)(row0 + ROWS_PER_TILE) * NC);
        #pragma unroll
        for (int i = tid; i < TILE_V4; i += TPB) cp_async16(s0 + i * 16, g0 + i);
        cp_commit();
        #pragma unroll
        for (int i = tid; i < TILE_V4; i += TPB) cp_async16(s1 + i * 16, g1 + i);
        cp_commit();

        // ---- tile A (tile B copy still in flight) ----
        cp_wait<1>();
        __syncwarp();
        #pragma unroll
        for (int i = 0; i < NC; i++) rr[i] = sbuf[0][tid * NC + i];

        float Kv = levdur(rr, a);

        // stage output A into the consumed buffer (owner-only rows)
        sbuf[0][tid * NC + 0] = Kv;
        #pragma unroll
        for (int i = 0; i < M_ORD; i++) sbuf[0][tid * NC + 1 + i] = a[i];
        __syncwarp();

        // coalesced store of tile A
        float4* o0 = reinterpret_cast<float4*>(out + (size_t)row0 * NC);
        const float4* sb0 = reinterpret_cast<const float4*>(&sbuf[0][0]);
        #pragma unroll
        for (int i = tid; i < TILE_V4; i += TPB) o0[i] = sb0[i];

        // ---- tile B ----
        cp_wait<0>();
        __syncwarp();
        #pragma unroll
        for (int i = 0; i < NC; i++) rr[i] = sbuf[1][tid * NC + i];

        Kv = levdur(rr, a);

        sbuf[1][tid * NC + 0] = Kv;
        #pragma unroll
        for (int i = 0; i < M_ORD; i++) sbuf[1][tid * NC + 1 + i] = a[i];
        __syncwarp();

        float4* o1 = reinterpret_cast<float4*>(
            out + (size_t)(row0 + ROWS_PER_TILE) * NC);
        const float4* sb1 = reinterpret_cast<const float4*>(&sbuf[1][0]);
        #pragma unroll
        for (int i = tid; i < TILE_V4; i += TPB) o1[i] = sb1[i];
    } else {
        // generic tail path (not hit for BATCH=262144)
        #pragma unroll
        for (int t = 0; t < 2; t++) {
            int row = row0 + t * ROWS_PER_TILE + tid;
            if (row >= nrows) continue;
            #pragma unroll
            for (int i = 0; i < NC; i++) rr[i] = r[(size_t)row * NC + i];
            float Kv = levdur(rr, a);
            out[(size_t)row * NC + 0] = Kv;
            #pragma unroll
            for (int i = 0; i < M_ORD; i++)
                out[(size_t)row * NC + 1 + i] = a[i];
        }
    }
}

extern "C" void kernel_launch(void* const* d_in, const int* in_sizes, int n_in,
                              void* d_out, int out_size)
{
    const float* r = (const float*)d_in[0];
    float* out = (float*)d_out;
    const int nrows = in_sizes[0] / NC;
    const int grid = (nrows + RPB - 1) / RPB;
    levinson_durbin_kernel<<<grid, TPB>>>(r, out, nrows);
}

// round 9
// speedup vs baseline: 1.1582x; 1.0176x over previous
#include <cuda_runtime.h>
#include <cuda_bf16.h>

// Levinson-Durbin, M=24. ONE row per thread; each WARP is fully autonomous
// (own cp.async group, own smem half, __syncwarp only). TPB=64 so two warps
// share one CTA slot -> dodges the 32-CTA/SM slot limit that capped R6.
// out[row] = [K, a0..a23],  R a = -r1,  K = sqrt(E_24).
//
// R8 design:
//  - __launch_bounds__(64,18) caps regs at 56 -> RF allows ~36 resident
//    warps/SM (was 33 at 61 regs, achieved 24.5). Mild cap: ~few one-shot
//    spills only.
//  - warp-private tiles: no __syncthreads, uncorrelated memory waits.
//  - adaptive split dot, pipelined rcp(-E), E += k*acc, sqrt.approx.

constexpr int M_ORD = 24;
constexpr int NC    = M_ORD + 1;               // 25
constexpr int TPB   = 64;
constexpr int WARPS = TPB / 32;                // 2
constexpr int ROWS_PER_WARP = 32;
constexpr int RPB   = TPB;                     // 64 rows per CTA (32/warp)
constexpr int WTILE_FLOATS = ROWS_PER_WARP * NC;   // 800
constexpr int WTILE_V4     = WTILE_FLOATS / 4;     // 200

__device__ __forceinline__ void cp_async16(unsigned saddr, const void* gaddr) {
    asm volatile("cp.async.cg.shared.global [%0], [%1], 16;"
                 :: "r"(saddr), "l"(gaddr));
}
__device__ __forceinline__ void cp_commit() {
    asm volatile("cp.async.commit_group;");
}
template <int N>
__device__ __forceinline__ void cp_wait() {
    asm volatile("cp.async.wait_group %0;" :: "n"(N));
}
// -(1/x): negation folded into the MUFU operand
__device__ __forceinline__ float nrcp(float x) {
    float y; asm("rcp.approx.f32 %0, %1;" : "=f"(y) : "f"(-x)); return y;
}
__device__ __forceinline__ float fsqrt_fast(float x) {
    float y; asm("sqrt.approx.f32 %0, %1;" : "=f"(y) : "f"(x)); return y;
}

// Full Levinson-Durbin recursion; returns K = sqrt(E_M), fills a[0..23].
__device__ __forceinline__ float levdur(const float rr[NC], float a[M_ORD]) {
    float E     = rr[0];
    float ninvE = nrcp(E);                     // -1/E, pipelined one iter ahead
    #pragma unroll
    for (int m = 0; m < M_ORD; m++) {
        float acc;
        if (m <= 4) {
            // tiny dots: single serial accumulator (no join add)
            float s0 = rr[m + 1];
            #pragma unroll
            for (int i = 0; i < m; i++) s0 = fmaf(a[i], rr[m - i], s0);
            acc = s0;
        } else if (m <= 10) {
            // short dots: 2-way split (1 reduction add)
            float s0 = rr[m + 1], s1 = 0.0f;
            #pragma unroll
            for (int i = 0; i + 1 < m; i += 2) {
                s0 = fmaf(a[i    ], rr[m - i    ], s0);
                s1 = fmaf(a[i + 1], rr[m - i - 1], s1);
            }
            if (m & 1) s0 = fmaf(a[m - 1], rr[1], s0);
            acc = s0 + s1;
        } else {
            // long dots: 4-way split (3 reduction adds, short chain)
            float s0 = rr[m + 1], s1 = 0.0f, s2 = 0.0f, s3 = 0.0f;
            #pragma unroll
            for (int i = 0; i + 3 < m; i += 4) {
                s0 = fmaf(a[i    ], rr[m - i    ], s0);
                s1 = fmaf(a[i + 1], rr[m - i - 1], s1);
                s2 = fmaf(a[i + 2], rr[m - i - 2], s2);
                s3 = fmaf(a[i + 3], rr[m - i - 3], s3);
            }
            {
                int i = m & ~3;
                if (i     < m) s0 = fmaf(a[i    ], rr[m - i    ], s0);
                if (i + 1 < m) s1 = fmaf(a[i + 1], rr[m - i - 1], s1);
                if (i + 2 < m) s2 = fmaf(a[i + 2], rr[m - i - 2], s2);
            }
            acc = (s0 + s1) + (s2 + s3);
        }

        float k = acc * ninvE;                 // k = -acc/E (MUFU latency hidden)

        // symmetric in-place update: a_i' = a_i + k * a_{m-1-i}
        #pragma unroll
        for (int i = 0; i < m / 2; i++) {
            float t = a[i];
            float u = a[m - 1 - i];
            a[i]         = fmaf(k, u, t);
            a[m - 1 - i] = fmaf(k, t, u);
        }
        if (m & 1) {
            float t = a[m / 2];
            a[m / 2] = fmaf(k, t, t);
        }
        a[m] = k;

        E     = fmaf(k, acc, E);               // E *= (1 - k^2)
        ninvE = nrcp(E);                       // hides under next dot
    }
    return fsqrt_fast(E);
}

__global__ __launch_bounds__(TPB, 18)          // caps regs at 56
void levinson_durbin_kernel(const float* __restrict__ r,
                            float* __restrict__ out,
                            int nrows)
{
    __shared__ float sbuf[WARPS][WTILE_FLOATS];   // 6.4 KB
    const int lane = threadIdx.x & 31;
    const int wid  = threadIdx.x >> 5;
    // this warp's 32-row tile
    const int wrow0 = blockIdx.x * RPB + wid * ROWS_PER_WARP;

    float rr[NC];
    float a[M_ORD];

    if (wrow0 + ROWS_PER_WARP <= nrows) {
        // ---- warp-private async prefetch of its 32-row tile ----
        unsigned s = (unsigned)__cvta_generic_to_shared(&sbuf[wid][0]);
        const float4* g = reinterpret_cast<const float4*>(r + (size_t)wrow0 * NC);
        #pragma unroll
        for (int i = lane; i < WTILE_V4; i += 32) cp_async16(s + i * 16, g + i);
        cp_commit();
        cp_wait<0>();
        __syncwarp();

        // stride-25 (odd) per-thread reads: bank-conflict-free
        #pragma unroll
        for (int i = 0; i < NC; i++) rr[i] = sbuf[wid][lane * NC + i];

        float Kv = levdur(rr, a);

        // stage output into own row (owner-only writes)
        sbuf[wid][lane * NC + 0] = Kv;
        #pragma unroll
        for (int i = 0; i < M_ORD; i++) sbuf[wid][lane * NC + 1 + i] = a[i];
        __syncwarp();

        // warp-private coalesced vector store
        float4* o = reinterpret_cast<float4*>(out + (size_t)wrow0 * NC);
        const float4* sb = reinterpret_cast<const float4*>(&sbuf[wid][0]);
        #pragma unroll
        for (int i = lane; i < WTILE_V4; i += 32) o[i] = sb[i];
    } else {
        // generic tail path (not hit for BATCH=262144)
        int row = wrow0 + lane;
        if (row < nrows) {
            #pragma unroll
            for (int i = 0; i < NC; i++) rr[i] = r[(size_t)row * NC + i];
            float Kv = levdur(rr, a);
            out[(size_t)row * NC + 0] = Kv;
            #pragma unroll
            for (int i = 0; i < M_ORD; i++)
                out[(size_t)row * NC + 1 + i] = a[i];
        }
    }
}

extern "C" void kernel_launch(void* const* d_in, const int* in_sizes, int n_in,
                              void* d_out, int out_size)
{
    const float* r = (const float*)d_in[0];
    float* out = (float*)d_out;
    const int nrows = in_sizes[0] / NC;
    const int grid = (nrows + RPB - 1) / RPB;
    levinson_durbin_kernel<<<grid, TPB>>>(r, out, nrows);
}